// round 11
// baseline (speedup 1.0000x reference)
#include <cuda_runtime.h>

#define D_DIM 64
#define H_DIM 256
#define W_DIM 256
#define PLANE (H_DIM * W_DIM)
#define D_CHUNK 8   // outputs per block along D (4 shared pairs)

// compare-exchange: a=min, b=max
__device__ __forceinline__ void s2(float& a, float& b) {
    float t = fminf(a, b);
    b = fmaxf(a, b);
    a = t;
}

// Optimal 9-input sorting network: 25 comparators, depth 7.
__device__ __forceinline__ void sort9(float* v) {
    s2(v[0],v[3]); s2(v[1],v[7]); s2(v[2],v[5]); s2(v[4],v[8]);
    s2(v[0],v[7]); s2(v[2],v[4]); s2(v[3],v[8]); s2(v[5],v[6]);
    s2(v[0],v[2]); s2(v[1],v[3]); s2(v[4],v[5]); s2(v[7],v[8]);
    s2(v[1],v[4]); s2(v[3],v[6]); s2(v[5],v[7]);
    s2(v[0],v[1]); s2(v[2],v[4]); s2(v[3],v[5]); s2(v[6],v[8]);
    s2(v[2],v[3]); s2(v[4],v[5]); s2(v[6],v[7]);
    s2(v[1],v[2]); s2(v[3],v[4]); s2(v[5],v[6]);
}

// ---- Batcher odd-even merges of two sorted arrays ----
__device__ __forceinline__ void merge11(const float* a, const float* b, float* c) {
    c[0] = a[0]; c[1] = b[0]; s2(c[0], c[1]);
}
__device__ __forceinline__ void merge22(const float* a, const float* b, float* c) {
    float ae[1] = {a[0]}, be[1] = {b[0]}, ao[1] = {a[1]}, bo[1] = {b[1]};
    float e[2], o[2];
    merge11(ae, be, e); merge11(ao, bo, o);
    c[0] = e[0];
    c[1] = o[0]; c[2] = e[1]; s2(c[1], c[2]);
    c[3] = o[1];
}
__device__ __forceinline__ void merge33(const float* a, const float* b, float* c) {
    float ae[2] = {a[0], a[2]}, be[2] = {b[0], b[2]};
    float ao[1] = {a[1]},       bo[1] = {b[1]};
    float e[4], o[2];
    merge22(ae, be, e); merge11(ao, bo, o);
    c[0] = e[0];
    c[1] = o[0]; c[2] = e[1]; s2(c[1], c[2]);
    c[3] = o[1]; c[4] = e[2]; s2(c[3], c[4]);
    c[5] = e[3];
}
__device__ __forceinline__ void merge44(const float* a, const float* b, float* c) {
    float ae[2] = {a[0], a[2]}, be[2] = {b[0], b[2]};
    float ao[2] = {a[1], a[3]}, bo[2] = {b[1], b[3]};
    float e[4], o[4];
    merge22(ae, be, e); merge22(ao, bo, o);
    c[0] = e[0];
    c[1] = o[0]; c[2] = e[1]; s2(c[1], c[2]);
    c[3] = o[1]; c[4] = e[2]; s2(c[3], c[4]);
    c[5] = o[2]; c[6] = e[3]; s2(c[5], c[6]);
    c[7] = o[3];
}
__device__ __forceinline__ void merge55(const float* a, const float* b, float* c) {
    float ae[3] = {a[0], a[2], a[4]}, be[3] = {b[0], b[2], b[4]};
    float ao[2] = {a[1], a[3]},       bo[2] = {b[1], b[3]};
    float e[6], o[4];
    merge33(ae, be, e); merge22(ao, bo, o);
    c[0] = e[0];
#pragma unroll
    for (int i = 1; i <= 4; ++i) { c[2*i-1] = o[i-1]; c[2*i] = e[i]; s2(c[2*i-1], c[2*i]); }
    c[9] = e[5];
}
// Full merge of two sorted 9s into sorted 18; only c[4..13] are consumed,
// comparators feeding only the ends are dead-coded by ptxas.
__device__ __forceinline__ void merge99(const float* a, const float* b, float* c) {
    float ae[5] = {a[0], a[2], a[4], a[6], a[8]};
    float be[5] = {b[0], b[2], b[4], b[6], b[8]};
    float ao[4] = {a[1], a[3], a[5], a[7]};
    float bo[4] = {b[1], b[3], b[5], b[7]};
    float e[10], o[8];
    merge55(ae, be, e); merge44(ao, bo, o);
    c[0] = e[0];
#pragma unroll
    for (int i = 1; i <= 8; ++i) { c[2*i-1] = o[i-1]; c[2*i] = e[i]; s2(c[2*i-1], c[2*i]); }
    c[17] = e[9];
}

// 10th smallest of sorted X[0..8] ∪ sorted T[0..9]  (== median of the 27-window).
// Closed form: max( T[0], max_i min(X[i], T[9-i]) ).
__device__ __forceinline__ float select10(const float* X, const float* T) {
    float c0 = T[0];
    float c1 = fminf(X[0], T[9]);
    float c2 = fminf(X[1], T[8]);
    float c3 = fminf(X[2], T[7]);
    float c4 = fminf(X[3], T[6]);
    float c5 = fminf(X[4], T[5]);
    float c6 = fminf(X[5], T[4]);
    float c7 = fminf(X[6], T[3]);
    float c8 = fminf(X[7], T[2]);
    float c9 = fminf(X[8], T[1]);
    float m01 = fmaxf(c0, c1), m23 = fmaxf(c2, c3);
    float m45 = fmaxf(c4, c5), m67 = fmaxf(c6, c7);
    float m89 = fmaxf(c8, c9);
    return fmaxf(fmaxf(fmaxf(m01, m23), fmaxf(m45, m67)), m89);
}

// Load the 3x3 (h,w) neighborhood of one D-plane with zero padding.
// Ternary form -> constant immediate LDG offsets + hoisted predicates.
__device__ __forceinline__ void load9(const float* __restrict__ q, float* P,
                                      bool hm, bool hp, bool wm, bool wp) {
    P[0] = (hm && wm) ? __ldg(q - W_DIM - 1) : 0.0f;
    P[1] = (hm)       ? __ldg(q - W_DIM)     : 0.0f;
    P[2] = (hm && wp) ? __ldg(q - W_DIM + 1) : 0.0f;
    P[3] = (wm)       ? __ldg(q - 1)         : 0.0f;
    P[4] =              __ldg(q);
    P[5] = (wp)       ? __ldg(q + 1)         : 0.0f;
    P[6] = (hp && wm) ? __ldg(q + W_DIM - 1) : 0.0f;
    P[7] = (hp)       ? __ldg(q + W_DIM)     : 0.0f;
    P[8] = (hp && wp) ? __ldg(q + W_DIM + 1) : 0.0f;
}

// Non-faulting, register-free L1 prefetch of the 3 rows of plane base q.
// Caller guarantees q-W_DIM and q+W_DIM are inside the allocation.
__device__ __forceinline__ void prefetch3(const float* q) {
    asm volatile("prefetch.global.L1 [%0];" :: "l"(q - W_DIM));
    asm volatile("prefetch.global.L1 [%0];" :: "l"(q));
    asm volatile("prefetch.global.L1 [%0];" :: "l"(q + W_DIM));
}

__global__ void __launch_bounds__(128, 10)
median3d_kernel(const float* __restrict__ x, float* __restrict__ y) {
    const int w = blockIdx.x * 128 + threadIdx.x;   // 0..255
    const int h = blockIdx.y;                       // 0..255
    const int d0 = blockIdx.z * D_CHUNK;

    const bool wm = (w > 0), wp = (w < W_DIM - 1);
    const bool hm = (h > 0), hp = (h < H_DIM - 1);

    const float* p0 = x + (size_t)h * W_DIM + w;      // input base at plane 0
    const float* pb = p0 + (size_t)d0 * PLANE;        // input base at plane d0
    float* ob = y + (size_t)d0 * PLANE + (size_t)h * W_DIM + w;  // output base

    float Pm[9], P0[9], P1[9], P2[9];   // sorted planes d-1, d, d+1, d+2
    float c[18];

    // plane d0-1 (zero pad if d0 == 0)
    if (d0 == 0) {
#pragma unroll
        for (int i = 0; i < 9; ++i) Pm[i] = 0.0f;
    } else {
        load9(pb - PLANE, Pm, hm, hp, wm, wp);
        sort9(Pm);
    }
    // plane d0
    load9(pb, P0, hm, hp, wm, wp);
    sort9(P0);

#pragma unroll
    for (int pp = 0; pp < D_CHUNK / 2; ++pp) {
        const int dd = 2 * pp;          // pair (d0+dd, d0+dd+1)

        // Warm L1 for the NEXT iteration's planes (dd+3, dd+4), clamped to the
        // last plane. Clamped index >= 3, so the +-W_DIM row prefetches stay
        // inside the allocation. prefetch.global.L1 uses no registers and sets
        // no scoreboard — pure latency hiding.
        {
            int k3 = d0 + dd + 3; if (k3 > D_DIM - 1) k3 = D_DIM - 1;
            int k4 = d0 + dd + 4; if (k4 > D_DIM - 1) k4 = D_DIM - 1;
            prefetch3(p0 + (size_t)k3 * PLANE);
            prefetch3(p0 + (size_t)k4 * PLANE);
        }

        // plane d0+dd+1 (always exists) — sorted
        load9(pb + (size_t)(dd + 1) * PLANE, P1, hm, hp, wm, wp);
        sort9(P1);

        // plane d0+dd+2 (zero pad if == D_DIM) — sorted
        if (d0 + dd + 2 < D_DIM) {
            load9(pb + (size_t)(dd + 2) * PLANE, P2, hm, hp, wm, wp);
            sort9(P2);
        } else {
#pragma unroll
            for (int i = 0; i < 9; ++i) P2[i] = 0.0f;
        }

        // shared sorted merge of the pair's planes; middle 10 = c[4..13]
        merge99(P0, P1, c);

        // two independent rank selections (high ILP)
        ob[(size_t)dd * PLANE]       = select10(Pm, c + 4);
        ob[(size_t)(dd + 1) * PLANE] = select10(P2, c + 4);

        // slide by 2: Pm <- P1, P0 <- P2 (register-renamed under full unroll)
#pragma unroll
        for (int i = 0; i < 9; ++i) { Pm[i] = P1[i]; P0[i] = P2[i]; }
    }
}

extern "C" void kernel_launch(void* const* d_in, const int* in_sizes, int n_in,
                              void* d_out, int out_size) {
    const float* x = (const float*)d_in[0];
    float* y = (float*)d_out;
    dim3 block(128, 1, 1);
    dim3 grid(W_DIM / 128, H_DIM, D_DIM / D_CHUNK);  // (2, 256, 8) = 4096 CTAs
    median3d_kernel<<<grid, block>>>(x, y);
}

// round 12
// speedup vs baseline: 1.0718x; 1.0718x over previous
#include <cuda_runtime.h>

#define D_DIM 64
#define H_DIM 256
#define W_DIM 256
#define PLANE (H_DIM * W_DIM)
#define D_CHUNK 8   // outputs per block along D (4 shared pairs)

// compare-exchange: a=min, b=max
__device__ __forceinline__ void s2(float& a, float& b) {
    float t = fminf(a, b);
    b = fmaxf(a, b);
    a = t;
}

// Optimal 9-input sorting network: 25 comparators, depth 7.
__device__ __forceinline__ void sort9(float* v) {
    s2(v[0],v[3]); s2(v[1],v[7]); s2(v[2],v[5]); s2(v[4],v[8]);
    s2(v[0],v[7]); s2(v[2],v[4]); s2(v[3],v[8]); s2(v[5],v[6]);
    s2(v[0],v[2]); s2(v[1],v[3]); s2(v[4],v[5]); s2(v[7],v[8]);
    s2(v[1],v[4]); s2(v[3],v[6]); s2(v[5],v[7]);
    s2(v[0],v[1]); s2(v[2],v[4]); s2(v[3],v[5]); s2(v[6],v[8]);
    s2(v[2],v[3]); s2(v[4],v[5]); s2(v[6],v[7]);
    s2(v[1],v[2]); s2(v[3],v[4]); s2(v[5],v[6]);
}

// ---- Batcher odd-even merges of two sorted arrays ----
__device__ __forceinline__ void merge11(const float* a, const float* b, float* c) {
    c[0] = a[0]; c[1] = b[0]; s2(c[0], c[1]);
}
__device__ __forceinline__ void merge22(const float* a, const float* b, float* c) {
    float ae[1] = {a[0]}, be[1] = {b[0]}, ao[1] = {a[1]}, bo[1] = {b[1]};
    float e[2], o[2];
    merge11(ae, be, e); merge11(ao, bo, o);
    c[0] = e[0];
    c[1] = o[0]; c[2] = e[1]; s2(c[1], c[2]);
    c[3] = o[1];
}
__device__ __forceinline__ void merge33(const float* a, const float* b, float* c) {
    float ae[2] = {a[0], a[2]}, be[2] = {b[0], b[2]};
    float ao[1] = {a[1]},       bo[1] = {b[1]};
    float e[4], o[2];
    merge22(ae, be, e); merge11(ao, bo, o);
    c[0] = e[0];
    c[1] = o[0]; c[2] = e[1]; s2(c[1], c[2]);
    c[3] = o[1]; c[4] = e[2]; s2(c[3], c[4]);
    c[5] = e[3];
}
__device__ __forceinline__ void merge44(const float* a, const float* b, float* c) {
    float ae[2] = {a[0], a[2]}, be[2] = {b[0], b[2]};
    float ao[2] = {a[1], a[3]}, bo[2] = {b[1], b[3]};
    float e[4], o[4];
    merge22(ae, be, e); merge22(ao, bo, o);
    c[0] = e[0];
    c[1] = o[0]; c[2] = e[1]; s2(c[1], c[2]);
    c[3] = o[1]; c[4] = e[2]; s2(c[3], c[4]);
    c[5] = o[2]; c[6] = e[3]; s2(c[5], c[6]);
    c[7] = o[3];
}
__device__ __forceinline__ void merge55(const float* a, const float* b, float* c) {
    float ae[3] = {a[0], a[2], a[4]}, be[3] = {b[0], b[2], b[4]};
    float ao[2] = {a[1], a[3]},       bo[2] = {b[1], b[3]};
    float e[6], o[4];
    merge33(ae, be, e); merge22(ao, bo, o);
    c[0] = e[0];
#pragma unroll
    for (int i = 1; i <= 4; ++i) { c[2*i-1] = o[i-1]; c[2*i] = e[i]; s2(c[2*i-1], c[2*i]); }
    c[9] = e[5];
}
// Full merge of two sorted 9s into sorted 18; only c[4..13] are consumed,
// comparators feeding only the ends are dead-coded by ptxas.
__device__ __forceinline__ void merge99(const float* a, const float* b, float* c) {
    float ae[5] = {a[0], a[2], a[4], a[6], a[8]};
    float be[5] = {b[0], b[2], b[4], b[6], b[8]};
    float ao[4] = {a[1], a[3], a[5], a[7]};
    float bo[4] = {b[1], b[3], b[5], b[7]};
    float e[10], o[8];
    merge55(ae, be, e); merge44(ao, bo, o);
    c[0] = e[0];
#pragma unroll
    for (int i = 1; i <= 8; ++i) { c[2*i-1] = o[i-1]; c[2*i] = e[i]; s2(c[2*i-1], c[2*i]); }
    c[17] = e[9];
}

// 10th smallest of sorted X[0..8] ∪ sorted T[0..9]  (== median of the 27-window).
// Closed form: max( T[0], max_i min(X[i], T[9-i]) ).
__device__ __forceinline__ float select10(const float* X, const float* T) {
    float c0 = T[0];
    float c1 = fminf(X[0], T[9]);
    float c2 = fminf(X[1], T[8]);
    float c3 = fminf(X[2], T[7]);
    float c4 = fminf(X[3], T[6]);
    float c5 = fminf(X[4], T[5]);
    float c6 = fminf(X[5], T[4]);
    float c7 = fminf(X[6], T[3]);
    float c8 = fminf(X[7], T[2]);
    float c9 = fminf(X[8], T[1]);
    float m01 = fmaxf(c0, c1), m23 = fmaxf(c2, c3);
    float m45 = fmaxf(c4, c5), m67 = fmaxf(c6, c7);
    float m89 = fmaxf(c8, c9);
    return fmaxf(fmaxf(fmaxf(m01, m23), fmaxf(m45, m67)), m89);
}

// Load the 3x3 (h,w) neighborhood of one D-plane with zero padding and an
// extra whole-plane validity predicate v (folded into the existing hoisted
// predicates; LDG offsets stay compile-time immediates).
__device__ __forceinline__ void load9v(const float* __restrict__ q, float* P,
                                       bool hm, bool hp, bool wm, bool wp, bool v) {
    P[0] = (v && hm && wm) ? __ldg(q - W_DIM - 1) : 0.0f;
    P[1] = (v && hm)       ? __ldg(q - W_DIM)     : 0.0f;
    P[2] = (v && hm && wp) ? __ldg(q - W_DIM + 1) : 0.0f;
    P[3] = (v && wm)       ? __ldg(q - 1)         : 0.0f;
    P[4] = (v)             ? __ldg(q)             : 0.0f;
    P[5] = (v && wp)       ? __ldg(q + 1)         : 0.0f;
    P[6] = (v && hp && wm) ? __ldg(q + W_DIM - 1) : 0.0f;
    P[7] = (v && hp)       ? __ldg(q + W_DIM)     : 0.0f;
    P[8] = (v && hp && wp) ? __ldg(q + W_DIM + 1) : 0.0f;
}

__global__ void __launch_bounds__(128, 10)
median3d_kernel(const float* __restrict__ x, float* __restrict__ y) {
    const int w = blockIdx.x * 128 + threadIdx.x;   // 0..255
    const int h = blockIdx.y;                       // 0..255
    const int d0 = blockIdx.z * D_CHUNK;

    const bool wm = (w > 0), wp = (w < W_DIM - 1);
    const bool hm = (h > 0), hp = (h < H_DIM - 1);

    const float* p0 = x + (size_t)h * W_DIM + w;      // input base at plane 0
    const float* pb = p0 + (size_t)d0 * PLANE;        // input base at plane d0
    float* ob = y + (size_t)d0 * PLANE + (size_t)h * W_DIM + w;  // output base

    float Pm[9], P0[9], P1[9], P2[9];   // sorted planes d-1, d, d+1, d+2
    float c[18];

    // plane d0-1 (zero pad if d0 == 0) and plane d0 — batched loads
    load9v(pb - PLANE, Pm, hm, hp, wm, wp, d0 != 0);  // pb-PLANE legal iff d0>0; predicated out otherwise, but clamp for safety:
    // NOTE: when d0==0, pb-PLANE == x - PLANE is never dereferenced (all 9
    // predicates false) — predicated-off LDGs do not issue addresses.
    load9v(pb, P0, hm, hp, wm, wp, true);
    sort9(Pm);
    sort9(P0);

#pragma unroll
    for (int pp = 0; pp < D_CHUNK / 2; ++pp) {
        const int dd = 2 * pp;          // pair (d0+dd, d0+dd+1)

        // Batch BOTH planes' 18 predicated loads up front (branch-free):
        // plane d0+dd+1 always exists; plane d0+dd+2 may be the zero pad.
        const bool v2 = (d0 + dd + 2 < D_DIM);
        // Clamped pointer keeps the address legal even when predicated off.
        const float* q2 = pb + (size_t)(v2 ? (dd + 2) : (dd + 1)) * PLANE;

        load9v(pb + (size_t)(dd + 1) * PLANE, P1, hm, hp, wm, wp, true);
        load9v(q2, P2, hm, hp, wm, wp, v2);

        sort9(P1);
        sort9(P2);                      // zeros sort to zeros in pad case

        // shared sorted merge of the pair's planes; middle 10 = c[4..13]
        merge99(P0, P1, c);

        // two independent rank selections (high ILP)
        ob[(size_t)dd * PLANE]       = select10(Pm, c + 4);
        ob[(size_t)(dd + 1) * PLANE] = select10(P2, c + 4);

        // slide by 2: Pm <- P1, P0 <- P2 (register-renamed under full unroll)
#pragma unroll
        for (int i = 0; i < 9; ++i) { Pm[i] = P1[i]; P0[i] = P2[i]; }
    }
}

extern "C" void kernel_launch(void* const* d_in, const int* in_sizes, int n_in,
                              void* d_out, int out_size) {
    const float* x = (const float*)d_in[0];
    float* y = (float*)d_out;
    dim3 block(128, 1, 1);
    dim3 grid(W_DIM / 128, H_DIM, D_DIM / D_CHUNK);  // (2, 256, 8) = 4096 CTAs
    median3d_kernel<<<grid, block>>>(x, y);
}